// round 1
// baseline (speedup 1.0000x reference)
#include <cuda_runtime.h>
#include <cuda_bf16.h>
#include <math.h>

// Problem constants
#define NROWS 4096      // 2*B
#define D     512
#define HALF  2048      // B
#define NCB   32        // column blocks in GEMM grid (4096/128)

// -------- device scratch (no allocations allowed) --------
__device__ float4 g_zn4[NROWS * (D / 4)];          // normalized rows, 8 MB
__device__ float  g_partial[NROWS * NCB];          // per-(row, colblock) exp-sums, 512 KB
__device__ float  g_pos[NROWS];
__device__ float  g_diag[NROWS];

// ============================================================
// Kernel 1: normalize. One block per row, 128 threads, float4.
// ============================================================
__global__ void __launch_bounds__(128) normalize_k(const float* __restrict__ zi,
                                                   const float* __restrict__ zj)
{
    const int row = blockIdx.x;
    const float* src = (row < HALF) ? (zi + (size_t)row * D)
                                    : (zj + (size_t)(row - HALF) * D);
    const int t = threadIdx.x;
    float4 v = reinterpret_cast<const float4*>(src)[t];
    float ss = v.x * v.x + v.y * v.y + v.z * v.z + v.w * v.w;

    #pragma unroll
    for (int o = 16; o > 0; o >>= 1)
        ss += __shfl_down_sync(0xffffffffu, ss, o);

    __shared__ float red[4];
    if ((t & 31) == 0) red[t >> 5] = ss;
    __syncthreads();
    float tot = red[0] + red[1] + red[2] + red[3];

    float inv = 1.0f / fmaxf(sqrtf(tot), 1e-8f);
    float4 o4 = make_float4(v.x * inv, v.y * inv, v.z * inv, v.w * inv);
    g_zn4[(size_t)row * (D / 4) + t] = o4;
}

// ============================================================
// Kernel 2: diag + positive-pair dot products. Block per row.
// ============================================================
__global__ void __launch_bounds__(128) posdiag_k()
{
    const int row = blockIdx.x;
    const int p = (row + HALF) & (NROWS - 1);
    const int t = threadIdx.x;

    float4 a = g_zn4[(size_t)row * (D / 4) + t];
    float4 b = g_zn4[(size_t)p   * (D / 4) + t];

    float dd = a.x * a.x + a.y * a.y + a.z * a.z + a.w * a.w;
    float pp = a.x * b.x + a.y * b.y + a.z * b.z + a.w * b.w;

    #pragma unroll
    for (int o = 16; o > 0; o >>= 1) {
        dd += __shfl_down_sync(0xffffffffu, dd, o);
        pp += __shfl_down_sync(0xffffffffu, pp, o);
    }

    __shared__ float rd[4], rp[4];
    if ((t & 31) == 0) { rd[t >> 5] = dd; rp[t >> 5] = pp; }
    __syncthreads();
    if (t == 0) {
        g_diag[row] = rd[0] + rd[1] + rd[2] + rd[3];
        g_pos[row]  = rp[0] + rp[1] + rp[2] + rp[3];
    }
}

// ============================================================
// Kernel 3: 128x128x8-tiled fp32 GEMM (S = zn * zn^T) fused
// with exp(2*S) row-sum epilogue. 256 threads, 8x8 per thread.
// Deterministic: each block writes its own partial slot.
// ============================================================
__global__ void __launch_bounds__(256) gemm_expsum_k()
{
    __shared__ float As[8][128];
    __shared__ float Bs[8][128];

    const int tid  = threadIdx.x;
    const int tx   = tid & 15;      // 0..15 -> column group
    const int ty   = tid >> 4;      // 0..15 -> row group
    const int brow = blockIdx.y;
    const int bcol = blockIdx.x;

    const float* A = reinterpret_cast<const float*>(g_zn4) + (size_t)brow * 128 * D;
    const float* B = reinterpret_cast<const float*>(g_zn4) + (size_t)bcol * 128 * D;

    // tile-load mapping: 256 threads, each loads one float4 (4 k-values of one row)
    const int lrow = tid >> 1;            // 0..127
    const int lk   = (tid & 1) << 2;      // 0 or 4
    const float* aptr = A + (size_t)lrow * D + lk;
    const float* bptr = B + (size_t)lrow * D + lk;

    float acc[8][8];
    #pragma unroll
    for (int i = 0; i < 8; i++)
        #pragma unroll
        for (int j = 0; j < 8; j++) acc[i][j] = 0.0f;

    for (int k0 = 0; k0 < D; k0 += 8) {
        float4 a4 = *reinterpret_cast<const float4*>(aptr + k0);
        float4 b4 = *reinterpret_cast<const float4*>(bptr + k0);
        __syncthreads();   // previous tile fully consumed
        As[lk + 0][lrow] = a4.x; As[lk + 1][lrow] = a4.y;
        As[lk + 2][lrow] = a4.z; As[lk + 3][lrow] = a4.w;
        Bs[lk + 0][lrow] = b4.x; Bs[lk + 1][lrow] = b4.y;
        Bs[lk + 2][lrow] = b4.z; Bs[lk + 3][lrow] = b4.w;
        __syncthreads();

        #pragma unroll
        for (int k = 0; k < 8; k++) {
            float a[8], b[8];
            #pragma unroll
            for (int i = 0; i < 8; i++) a[i] = As[k][ty * 8 + i];
            #pragma unroll
            for (int j = 0; j < 8; j++) b[j] = Bs[k][tx * 8 + j];
            #pragma unroll
            for (int i = 0; i < 8; i++)
                #pragma unroll
                for (int j = 0; j < 8; j++)
                    acc[i][j] = fmaf(a[i], b[j], acc[i][j]);
        }
    }

    // Epilogue: per-row sum of exp(2*S) over this block's 128 columns.
    // Threads sharing a row-group are lanes tx=0..15 within a 16-lane shfl group.
    const int rowbase = brow * 128 + ty * 8;
    #pragma unroll
    for (int i = 0; i < 8; i++) {
        float rs = 0.0f;
        #pragma unroll
        for (int j = 0; j < 8; j++)
            rs += __expf(2.0f * acc[i][j]);
        rs += __shfl_down_sync(0xffffffffu, rs, 8, 16);
        rs += __shfl_down_sync(0xffffffffu, rs, 4, 16);
        rs += __shfl_down_sync(0xffffffffu, rs, 2, 16);
        rs += __shfl_down_sync(0xffffffffu, rs, 1, 16);
        if (tx == 0)
            g_partial[(size_t)(rowbase + i) * NCB + bcol] = rs;
    }
}

// ============================================================
// Kernel 4: finalize. Sum partials per row, apply diag/pos
// correction, log, mean over rows.
// ============================================================
__global__ void __launch_bounds__(1024) finalize_k(float* __restrict__ out)
{
    float acc = 0.0f;
    for (int r = threadIdx.x; r < NROWS; r += 1024) {
        const float* pr = g_partial + (size_t)r * NCB;
        float s = 0.0f;
        #pragma unroll
        for (int c = 0; c < NCB; c++) s += pr[c];
        float pos  = g_pos[r];
        float diag = g_diag[r];
        float tot  = s - __expf(2.0f * diag) + __expf(2.0f * pos);
        acc += logf(tot) - 2.0f * pos;
    }

    // block reduce
    #pragma unroll
    for (int o = 16; o > 0; o >>= 1)
        acc += __shfl_down_sync(0xffffffffu, acc, o);

    __shared__ float red[32];
    const int lane = threadIdx.x & 31, warp = threadIdx.x >> 5;
    if (lane == 0) red[warp] = acc;
    __syncthreads();
    if (warp == 0) {
        float v = (lane < 32) ? red[lane] : 0.0f;
        #pragma unroll
        for (int o = 16; o > 0; o >>= 1)
            v += __shfl_down_sync(0xffffffffu, v, o);
        if (lane == 0) out[0] = v / (float)NROWS;
    }
}

// ============================================================
extern "C" void kernel_launch(void* const* d_in, const int* in_sizes, int n_in,
                              void* d_out, int out_size)
{
    const float* zi = (const float*)d_in[0];
    const float* zj = (const float*)d_in[1];
    float* out = (float*)d_out;

    normalize_k<<<NROWS, 128>>>(zi, zj);
    posdiag_k<<<NROWS, 128>>>();
    dim3 grid(NCB, NROWS / 128);
    gemm_expsum_k<<<grid, 256>>>();
    finalize_k<<<1, 1024>>>(out);
}

// round 3
// speedup vs baseline: 6.8134x; 6.8134x over previous
#include <cuda_runtime.h>
#include <cuda_bf16.h>
#include <math.h>
#include <stdint.h>

// ---------------- problem constants ----------------
#define NROWS 4096      // 2*B
#define D     512
#define HALF  2048      // B
#define PSLOTS 64       // 32 column tiles * 2 warp-column halves

// ---------------- device scratch (no allocs) ----------------
__device__ __nv_bfloat16 g_zbf[NROWS * D];     // normalized rows, bf16 (4 MB)
__device__ float g_partial[NROWS * PSLOTS];    // exp row-sum partials (1 MB)
__device__ float g_pos[NROWS];
__device__ float g_diag[NROWS];
__device__ float g_blk[32];

// SMEM: two buffers, each A[128][72] + B[128][72] bf16 (pad 64->72 kills conflicts)
#define TILE_ELEMS (128 * 72)            // 9216 elems = 18432 bytes
#define BUF_BYTES  (2 * TILE_ELEMS * 2)  // A+B = 36864
#define SMEM_TOT   (2 * BUF_BYTES)       // 73728

__device__ __forceinline__ uint32_t smem_u32(const void* p) {
    uint32_t a;
    asm("{ .reg .u64 t; cvta.to.shared.u64 t, %1; cvt.u32.u64 %0, t; }" : "=r"(a) : "l"(p));
    return a;
}

// exp(2*s) for s in [-1,1]: (Taylor5(s/2))^4 — pure FMA pipe, no MUFU.
__device__ __forceinline__ float exp2S(float s) {
    float y = 0.5f * s;
    float p = fmaf(y, 8.3333333e-3f, 4.1666667e-2f);   // 1/120, 1/24
    p = fmaf(p, y, 1.6666667e-1f);
    p = fmaf(p, y, 0.5f);
    p = fmaf(p, y, 1.0f);
    p = fmaf(p, y, 1.0f);
    p = p * p;
    return p * p;
}

// ============================================================
// Kernel 1: normalize rows, write bf16.
// ============================================================
__global__ void __launch_bounds__(128) normalize_k(const float* __restrict__ zi,
                                                   const float* __restrict__ zj)
{
    const int row = blockIdx.x;
    const float* src = (row < HALF) ? (zi + (size_t)row * D)
                                    : (zj + (size_t)(row - HALF) * D);
    const int t = threadIdx.x;
    float4 v = reinterpret_cast<const float4*>(src)[t];
    float ss = v.x * v.x + v.y * v.y + v.z * v.z + v.w * v.w;

    #pragma unroll
    for (int o = 16; o > 0; o >>= 1)
        ss += __shfl_down_sync(0xffffffffu, ss, o);

    __shared__ float red[4];
    if ((t & 31) == 0) red[t >> 5] = ss;
    __syncthreads();
    float tot = red[0] + red[1] + red[2] + red[3];
    float inv = 1.0f / fmaxf(sqrtf(tot), 1e-8f);

    __nv_bfloat162* dst = reinterpret_cast<__nv_bfloat162*>(g_zbf + (size_t)row * D);
    dst[t * 2 + 0] = __float22bfloat162_rn(make_float2(v.x * inv, v.y * inv));
    dst[t * 2 + 1] = __float22bfloat162_rn(make_float2(v.z * inv, v.w * inv));
}

// ============================================================
// Kernel 2: diag + positive dot from the SAME bf16 values.
// ============================================================
__global__ void __launch_bounds__(128) posdiag_k()
{
    const int row = blockIdx.x;
    const int p = (row + HALF) & (NROWS - 1);
    const int t = threadIdx.x;

    const __nv_bfloat162* ar = reinterpret_cast<const __nv_bfloat162*>(g_zbf + (size_t)row * D);
    const __nv_bfloat162* br = reinterpret_cast<const __nv_bfloat162*>(g_zbf + (size_t)p * D);

    float dd = 0.0f, pp = 0.0f;
    #pragma unroll
    for (int q = 0; q < 2; q++) {
        float2 a = __bfloat1622float2(ar[t * 2 + q]);
        float2 b = __bfloat1622float2(br[t * 2 + q]);
        dd += a.x * a.x + a.y * a.y;
        pp += a.x * b.x + a.y * b.y;
    }
    #pragma unroll
    for (int o = 16; o > 0; o >>= 1) {
        dd += __shfl_down_sync(0xffffffffu, dd, o);
        pp += __shfl_down_sync(0xffffffffu, pp, o);
    }
    __shared__ float rd[4], rp[4];
    if ((t & 31) == 0) { rd[t >> 5] = dd; rp[t >> 5] = pp; }
    __syncthreads();
    if (t == 0) {
        g_diag[row] = rd[0] + rd[1] + rd[2] + rd[3];
        g_pos[row]  = rp[0] + rp[1] + rp[2] + rp[3];
    }
}

// ============================================================
// Kernel 3: bf16 mma.sync GEMM (128x128 tile, BK=64 double-
// buffered cp.async) + fused poly-exp(2S) row-sum epilogue.
// 256 threads = 8 warps as 4(m) x 2(n); warp tile 32x64.
// ============================================================
__global__ void __launch_bounds__(256, 2) gemm_expsum_k()
{
    extern __shared__ __align__(128) char smem[];
    const uint32_t sbase = smem_u32(smem);

    const int tid  = threadIdx.x;
    const int lane = tid & 31;
    const int wid  = tid >> 5;
    const int warp_m = wid >> 1;   // 0..3
    const int warp_n = wid & 1;    // 0..1
    const int brow = blockIdx.y;
    const int bcol = blockIdx.x;

    const __nv_bfloat16* Ab = g_zbf + (size_t)(brow * 128) * D;
    const __nv_bfloat16* Bb = g_zbf + (size_t)(bcol * 128) * D;

    // --- async tile loader: 1024 x 16B per tile, 256 threads ---
    auto load_chunk = [&](int c) {
        const uint32_t sa = sbase + (uint32_t)(c & 1) * BUF_BYTES;
        const uint32_t sb = sa + TILE_ELEMS * 2;
        const int k0 = c * 64;
        #pragma unroll
        for (int i = 0; i < 4; i++) {
            int idx = tid + i * 256;
            int row = idx >> 3, cc = idx & 7;
            uint32_t so = (uint32_t)(row * 72 + cc * 8) * 2u;
            const __nv_bfloat16* ga = Ab + (size_t)row * D + k0 + cc * 8;
            const __nv_bfloat16* gb = Bb + (size_t)row * D + k0 + cc * 8;
            asm volatile("cp.async.cg.shared.global [%0], [%1], 16;" :: "r"(sa + so), "l"(ga));
            asm volatile("cp.async.cg.shared.global [%0], [%1], 16;" :: "r"(sb + so), "l"(gb));
        }
        asm volatile("cp.async.commit_group;");
    };

    float acc[2][8][4];
    #pragma unroll
    for (int mf = 0; mf < 2; mf++)
        #pragma unroll
        for (int nf = 0; nf < 8; nf++)
            #pragma unroll
            for (int e = 0; e < 4; e++) acc[mf][nf][e] = 0.0f;

    load_chunk(0);

    #pragma unroll 1
    for (int c = 0; c < 8; c++) {
        if (c < 7) {
            load_chunk(c + 1);
            asm volatile("cp.async.wait_group 1;");
        } else {
            asm volatile("cp.async.wait_group 0;");
        }
        __syncthreads();

        const uint32_t sa = sbase + (uint32_t)(c & 1) * BUF_BYTES;
        const uint32_t sb = sa + TILE_ELEMS * 2;

        #pragma unroll
        for (int k16 = 0; k16 < 4; k16++) {
            uint32_t a[2][4];
            #pragma unroll
            for (int mf = 0; mf < 2; mf++) {
                int row = warp_m * 32 + mf * 16 + (lane & 15);
                int col = k16 * 16 + (lane >> 4) * 8;
                uint32_t addr = sa + (uint32_t)(row * 72 + col) * 2u;
                asm volatile("ldmatrix.sync.aligned.m8n8.x4.shared.b16 {%0,%1,%2,%3},[%4];"
                    : "=r"(a[mf][0]), "=r"(a[mf][1]), "=r"(a[mf][2]), "=r"(a[mf][3])
                    : "r"(addr));
            }
            #pragma unroll
            for (int nf16 = 0; nf16 < 4; nf16++) {
                // lanes 0-7: (n+0..7, klo) | 8-15: (n+0..7, khi)
                // 16-23: (n+8..15, klo)    | 24-31: (n+8..15, khi)
                int sub = lane >> 3, wi = lane & 7;
                int nrow = warp_n * 64 + nf16 * 16 + ((sub & 2) ? 8 : 0) + wi;
                int kcol = k16 * 16 + ((sub & 1) ? 8 : 0);
                uint32_t addr = sb + (uint32_t)(nrow * 72 + kcol) * 2u;
                uint32_t b0, b1, b2, b3;
                asm volatile("ldmatrix.sync.aligned.m8n8.x4.shared.b16 {%0,%1,%2,%3},[%4];"
                    : "=r"(b0), "=r"(b1), "=r"(b2), "=r"(b3) : "r"(addr));
                #pragma unroll
                for (int mf = 0; mf < 2; mf++) {
                    float* c0 = acc[mf][2 * nf16];
                    float* c1 = acc[mf][2 * nf16 + 1];
                    asm volatile(
                        "mma.sync.aligned.m16n8k16.row.col.f32.bf16.bf16.f32 "
                        "{%0,%1,%2,%3},{%4,%5,%6,%7},{%8,%9},{%0,%1,%2,%3};"
                        : "+f"(c0[0]), "+f"(c0[1]), "+f"(c0[2]), "+f"(c0[3])
                        : "r"(a[mf][0]), "r"(a[mf][1]), "r"(a[mf][2]), "r"(a[mf][3]),
                          "r"(b0), "r"(b1));
                    asm volatile(
                        "mma.sync.aligned.m16n8k16.row.col.f32.bf16.bf16.f32 "
                        "{%0,%1,%2,%3},{%4,%5,%6,%7},{%8,%9},{%0,%1,%2,%3};"
                        : "+f"(c1[0]), "+f"(c1[1]), "+f"(c1[2]), "+f"(c1[3])
                        : "r"(a[mf][0]), "r"(a[mf][1]), "r"(a[mf][2]), "r"(a[mf][3]),
                          "r"(b2), "r"(b3));
                }
            }
        }
        __syncthreads();
    }

    // --- epilogue: poly-exp + row sums ---
    // acc rows: warp_m*32 + mf*16 + (lane>>2) [+8 for e=2,3]; row-mates are lanes l^1,l^2.
    #pragma unroll
    for (int mf = 0; mf < 2; mf++) {
        float rlo = 0.0f, rhi = 0.0f;
        #pragma unroll
        for (int nf = 0; nf < 8; nf++) {
            rlo += exp2S(acc[mf][nf][0]) + exp2S(acc[mf][nf][1]);
            rhi += exp2S(acc[mf][nf][2]) + exp2S(acc[mf][nf][3]);
        }
        rlo += __shfl_xor_sync(0xffffffffu, rlo, 1);
        rlo += __shfl_xor_sync(0xffffffffu, rlo, 2);
        rhi += __shfl_xor_sync(0xffffffffu, rhi, 1);
        rhi += __shfl_xor_sync(0xffffffffu, rhi, 2);
        if ((lane & 3) == 0) {
            int r0 = brow * 128 + warp_m * 32 + mf * 16 + (lane >> 2);
            int slot = bcol * 2 + warp_n;
            g_partial[(size_t)r0 * PSLOTS + slot] = rlo;
            g_partial[(size_t)(r0 + 8) * PSLOTS + slot] = rhi;
        }
    }
}

// ============================================================
// Kernel 4a: per-row loss terms, one block per 128 rows.
// ============================================================
__global__ void __launch_bounds__(128) finalize1_k()
{
    const int row = blockIdx.x * 128 + threadIdx.x;
    const float* pr = g_partial + (size_t)row * PSLOTS;
    float s = 0.0f;
    #pragma unroll
    for (int c = 0; c < PSLOTS; c++) s += pr[c];
    float pos = g_pos[row], diag = g_diag[row];
    float tot = s - exp2S(diag) + exp2S(pos);
    float v = logf(tot) - 2.0f * pos;

    #pragma unroll
    for (int o = 16; o > 0; o >>= 1)
        v += __shfl_down_sync(0xffffffffu, v, o);
    __shared__ float red[4];
    if ((threadIdx.x & 31) == 0) red[threadIdx.x >> 5] = v;
    __syncthreads();
    if (threadIdx.x == 0)
        g_blk[blockIdx.x] = red[0] + red[1] + red[2] + red[3];
}

// ============================================================
// Kernel 4b: final reduce of 32 block sums.
// ============================================================
__global__ void __launch_bounds__(32) finalize2_k(float* __restrict__ out)
{
    float v = g_blk[threadIdx.x];
    #pragma unroll
    for (int o = 16; o > 0; o >>= 1)
        v += __shfl_down_sync(0xffffffffu, v, o);
    if (threadIdx.x == 0) out[0] = v / (float)NROWS;
}

// ============================================================
extern "C" void kernel_launch(void* const* d_in, const int* in_sizes, int n_in,
                              void* d_out, int out_size)
{
    const float* zi = (const float*)d_in[0];
    const float* zj = (const float*)d_in[1];
    float* out = (float*)d_out;

    cudaFuncSetAttribute(gemm_expsum_k,
                         cudaFuncAttributeMaxDynamicSharedMemorySize, SMEM_TOT);

    normalize_k<<<NROWS, 128>>>(zi, zj);
    posdiag_k<<<NROWS, 128>>>();
    dim3 grid(NROWS / 128, NROWS / 128);   // (32, 32)
    gemm_expsum_k<<<grid, 256, SMEM_TOT>>>();
    finalize1_k<<<32, 128>>>();
    finalize2_k<<<1, 32>>>(out);
}

// round 4
// speedup vs baseline: 10.9174x; 1.6023x over previous
#include <cuda_runtime.h>
#include <cuda_bf16.h>
#include <math.h>
#include <stdint.h>

// ---------------- problem constants ----------------
#define NROWS 4096      // 2*B
#define D     512
#define HALF  2048      // B
#define PSLOTS 64       // 32 column tiles * 2 halves

// ---------------- device scratch (no allocs) ----------------
__device__ __nv_bfloat16 g_zbf[NROWS * D];     // normalized rows, bf16 (4 MB)
__device__ float g_partial[NROWS * PSLOTS];    // exp row-sum partials (1 MB)
__device__ float g_pos[NROWS];
__device__ float g_diag[NROWS];
__device__ float g_blk[256];

// SMEM: two buffers, each A[128][72] + B[128][72] bf16
#define TILE_ELEMS (128 * 72)
#define BUF_BYTES  (2 * TILE_ELEMS * 2)  // 36864
#define SMEM_TOT   (2 * BUF_BYTES)       // 73728

__device__ __forceinline__ uint32_t smem_u32(const void* p) {
    uint32_t a;
    asm("{ .reg .u64 t; cvta.to.shared.u64 t, %1; cvt.u32.u64 %0, t; }" : "=r"(a) : "l"(p));
    return a;
}

// exp(2*s) for s in [-1,1]: (Taylor5(s/2))^4 — FMA pipe only.
__device__ __forceinline__ float exp2S(float s) {
    float y = 0.5f * s;
    float p = fmaf(y, 8.3333333e-3f, 4.1666667e-2f);
    p = fmaf(p, y, 1.6666667e-1f);
    p = fmaf(p, y, 0.5f);
    p = fmaf(p, y, 1.0f);
    p = fmaf(p, y, 1.0f);
    p = p * p;
    return p * p;
}

// ============================================================
// Kernel 1: fused normalize + pos/diag. One block per pair r.
// ============================================================
__global__ void __launch_bounds__(128) normpos_k(const float* __restrict__ zi,
                                                 const float* __restrict__ zj)
{
    const int r = blockIdx.x;          // 0..HALF-1
    const int t = threadIdx.x;

    float4 a = reinterpret_cast<const float4*>(zi + (size_t)r * D)[t];
    float4 b = reinterpret_cast<const float4*>(zj + (size_t)r * D)[t];

    float sa = a.x * a.x + a.y * a.y + a.z * a.z + a.w * a.w;
    float sb = b.x * b.x + b.y * b.y + b.z * b.z + b.w * b.w;
    #pragma unroll
    for (int o = 16; o > 0; o >>= 1) {
        sa += __shfl_down_sync(0xffffffffu, sa, o);
        sb += __shfl_down_sync(0xffffffffu, sb, o);
    }
    __shared__ float ra[4], rb[4];
    if ((t & 31) == 0) { ra[t >> 5] = sa; rb[t >> 5] = sb; }
    __syncthreads();
    float invA = 1.0f / fmaxf(sqrtf(ra[0] + ra[1] + ra[2] + ra[3]), 1e-8f);
    float invB = 1.0f / fmaxf(sqrtf(rb[0] + rb[1] + rb[2] + rb[3]), 1e-8f);

    __nv_bfloat162 a01 = __float22bfloat162_rn(make_float2(a.x * invA, a.y * invA));
    __nv_bfloat162 a23 = __float22bfloat162_rn(make_float2(a.z * invA, a.w * invA));
    __nv_bfloat162 b01 = __float22bfloat162_rn(make_float2(b.x * invB, b.y * invB));
    __nv_bfloat162 b23 = __float22bfloat162_rn(make_float2(b.z * invB, b.w * invB));

    __nv_bfloat162* da = reinterpret_cast<__nv_bfloat162*>(g_zbf + (size_t)r * D);
    __nv_bfloat162* db = reinterpret_cast<__nv_bfloat162*>(g_zbf + (size_t)(r + HALF) * D);
    da[t * 2 + 0] = a01; da[t * 2 + 1] = a23;
    db[t * 2 + 0] = b01; db[t * 2 + 1] = b23;

    // pos/diag from the SAME rounded values (matches GEMM's diagonal)
    float2 fa0 = __bfloat1622float2(a01), fa1 = __bfloat1622float2(a23);
    float2 fb0 = __bfloat1622float2(b01), fb1 = __bfloat1622float2(b23);
    float pp = fa0.x * fb0.x + fa0.y * fb0.y + fa1.x * fb1.x + fa1.y * fb1.y;
    float dA = fa0.x * fa0.x + fa0.y * fa0.y + fa1.x * fa1.x + fa1.y * fa1.y;
    float dB = fb0.x * fb0.x + fb0.y * fb0.y + fb1.x * fb1.x + fb1.y * fb1.y;
    #pragma unroll
    for (int o = 16; o > 0; o >>= 1) {
        pp += __shfl_down_sync(0xffffffffu, pp, o);
        dA += __shfl_down_sync(0xffffffffu, dA, o);
        dB += __shfl_down_sync(0xffffffffu, dB, o);
    }
    __shared__ float rp[4], rdA[4], rdB[4];
    if ((t & 31) == 0) { rp[t >> 5] = pp; rdA[t >> 5] = dA; rdB[t >> 5] = dB; }
    __syncthreads();
    if (t == 0) {
        float p4 = rp[0] + rp[1] + rp[2] + rp[3];
        g_pos[r] = p4; g_pos[r + HALF] = p4;
        g_diag[r] = rdA[0] + rdA[1] + rdA[2] + rdA[3];
        g_diag[r + HALF] = rdB[0] + rdB[1] + rdB[2] + rdB[3];
    }
}

// ============================================================
// Kernel 2: symmetric bf16 mma.sync GEMM. Only brow<=bcol tiles.
// Emits row-sums (brow tile) and, for off-diag blocks, col-sums
// (bcol tile) of exp(2S). 256 threads = 4(m) x 2(n) warps.
// ============================================================
__global__ void __launch_bounds__(256, 2) gemm_expsum_k()
{
    const int brow = blockIdx.y;
    const int bcol = blockIdx.x;
    if (brow > bcol) return;           // symmetry: skip lower triangle

    extern __shared__ __align__(128) char smem[];
    const uint32_t sbase = smem_u32(smem);

    const int tid  = threadIdx.x;
    const int lane = tid & 31;
    const int wid  = tid >> 5;
    const int warp_m = wid >> 1;
    const int warp_n = wid & 1;

    const __nv_bfloat16* Ab = g_zbf + (size_t)(brow * 128) * D;
    const __nv_bfloat16* Bb = g_zbf + (size_t)(bcol * 128) * D;

    auto load_chunk = [&](int c) {
        const uint32_t sa = sbase + (uint32_t)(c & 1) * BUF_BYTES;
        const uint32_t sb = sa + TILE_ELEMS * 2;
        const int k0 = c * 64;
        #pragma unroll
        for (int i = 0; i < 4; i++) {
            int idx = tid + i * 256;
            int row = idx >> 3, cc = idx & 7;
            uint32_t so = (uint32_t)(row * 72 + cc * 8) * 2u;
            const __nv_bfloat16* ga = Ab + (size_t)row * D + k0 + cc * 8;
            const __nv_bfloat16* gb = Bb + (size_t)row * D + k0 + cc * 8;
            asm volatile("cp.async.cg.shared.global [%0], [%1], 16;" :: "r"(sa + so), "l"(ga));
            asm volatile("cp.async.cg.shared.global [%0], [%1], 16;" :: "r"(sb + so), "l"(gb));
        }
        asm volatile("cp.async.commit_group;");
    };

    float acc[2][8][4];
    #pragma unroll
    for (int mf = 0; mf < 2; mf++)
        #pragma unroll
        for (int nf = 0; nf < 8; nf++)
            #pragma unroll
            for (int e = 0; e < 4; e++) acc[mf][nf][e] = 0.0f;

    load_chunk(0);

    #pragma unroll 1
    for (int c = 0; c < 8; c++) {
        if (c < 7) {
            load_chunk(c + 1);
            asm volatile("cp.async.wait_group 1;");
        } else {
            asm volatile("cp.async.wait_group 0;");
        }
        __syncthreads();

        const uint32_t sa = sbase + (uint32_t)(c & 1) * BUF_BYTES;
        const uint32_t sb = sa + TILE_ELEMS * 2;

        #pragma unroll
        for (int k16 = 0; k16 < 4; k16++) {
            uint32_t a[2][4];
            #pragma unroll
            for (int mf = 0; mf < 2; mf++) {
                int row = warp_m * 32 + mf * 16 + (lane & 15);
                int col = k16 * 16 + (lane >> 4) * 8;
                uint32_t addr = sa + (uint32_t)(row * 72 + col) * 2u;
                asm volatile("ldmatrix.sync.aligned.m8n8.x4.shared.b16 {%0,%1,%2,%3},[%4];"
                    : "=r"(a[mf][0]), "=r"(a[mf][1]), "=r"(a[mf][2]), "=r"(a[mf][3])
                    : "r"(addr));
            }
            #pragma unroll
            for (int nf16 = 0; nf16 < 4; nf16++) {
                int sub = lane >> 3, wi = lane & 7;
                int nrow = warp_n * 64 + nf16 * 16 + ((sub & 2) ? 8 : 0) + wi;
                int kcol = k16 * 16 + ((sub & 1) ? 8 : 0);
                uint32_t addr = sb + (uint32_t)(nrow * 72 + kcol) * 2u;
                uint32_t b0, b1, b2, b3;
                asm volatile("ldmatrix.sync.aligned.m8n8.x4.shared.b16 {%0,%1,%2,%3},[%4];"
                    : "=r"(b0), "=r"(b1), "=r"(b2), "=r"(b3) : "r"(addr));
                #pragma unroll
                for (int mf = 0; mf < 2; mf++) {
                    float* c0 = acc[mf][2 * nf16];
                    float* c1 = acc[mf][2 * nf16 + 1];
                    asm volatile(
                        "mma.sync.aligned.m16n8k16.row.col.f32.bf16.bf16.f32 "
                        "{%0,%1,%2,%3},{%4,%5,%6,%7},{%8,%9},{%0,%1,%2,%3};"
                        : "+f"(c0[0]), "+f"(c0[1]), "+f"(c0[2]), "+f"(c0[3])
                        : "r"(a[mf][0]), "r"(a[mf][1]), "r"(a[mf][2]), "r"(a[mf][3]),
                          "r"(b0), "r"(b1));
                    asm volatile(
                        "mma.sync.aligned.m16n8k16.row.col.f32.bf16.bf16.f32 "
                        "{%0,%1,%2,%3},{%4,%5,%6,%7},{%8,%9},{%0,%1,%2,%3};"
                        : "+f"(c1[0]), "+f"(c1[1]), "+f"(c1[2]), "+f"(c1[3])
                        : "r"(a[mf][0]), "r"(a[mf][1]), "r"(a[mf][2]), "r"(a[mf][3]),
                          "r"(b2), "r"(b3));
                }
            }
        }
        __syncthreads();
    }

    // --- epilogue: in-place exp, then row-sums (+ col-sums off-diag) ---
    #pragma unroll
    for (int mf = 0; mf < 2; mf++)
        #pragma unroll
        for (int nf = 0; nf < 8; nf++)
            #pragma unroll
            for (int e = 0; e < 4; e++)
                acc[mf][nf][e] = exp2S(acc[mf][nf][e]);

    // row-sums: rows in brow tile, 64-col halves per warp_n
    #pragma unroll
    for (int mf = 0; mf < 2; mf++) {
        float rlo = 0.0f, rhi = 0.0f;
        #pragma unroll
        for (int nf = 0; nf < 8; nf++) {
            rlo += acc[mf][nf][0] + acc[mf][nf][1];
            rhi += acc[mf][nf][2] + acc[mf][nf][3];
        }
        rlo += __shfl_xor_sync(0xffffffffu, rlo, 1);
        rlo += __shfl_xor_sync(0xffffffffu, rlo, 2);
        rhi += __shfl_xor_sync(0xffffffffu, rhi, 1);
        rhi += __shfl_xor_sync(0xffffffffu, rhi, 2);
        if ((lane & 3) == 0) {
            int r0 = brow * 128 + warp_m * 32 + mf * 16 + (lane >> 2);
            int slot = bcol * 2 + warp_n;
            g_partial[(size_t)r0 * PSLOTS + slot] = rlo;
            g_partial[(size_t)(r0 + 8) * PSLOTS + slot] = rhi;
        }
    }

    if (brow != bcol) {
        // col-sums: this block's columns = rows of bcol tile.
        // Per thread: sum its 4 row positions per column; butterfly over
        // lane>>2 (offsets 4,8,16) yields 32-row (one warp_m) col sums.
        float cs[16];
        #pragma unroll
        for (int nf = 0; nf < 8; nf++)
            #pragma unroll
            for (int e = 0; e < 2; e++)
                cs[nf * 2 + e] = acc[0][nf][e] + acc[0][nf][e + 2]
                               + acc[1][nf][e] + acc[1][nf][e + 2];
        #pragma unroll
        for (int i = 0; i < 16; i++) {
            cs[i] += __shfl_xor_sync(0xffffffffu, cs[i], 4);
            cs[i] += __shfl_xor_sync(0xffffffffu, cs[i], 8);
            cs[i] += __shfl_xor_sync(0xffffffffu, cs[i], 16);
        }
        float* scol = reinterpret_cast<float*>(smem);  // [4][128], tiles done
        __syncthreads();   // tile smem fully consumed by all warps
        if (lane < 4) {
            #pragma unroll
            for (int nf = 0; nf < 8; nf++)
                #pragma unroll
                for (int e = 0; e < 2; e++) {
                    int col = warp_n * 64 + (nf >> 1) * 16 + (nf & 1) * 8 + lane * 2 + e;
                    scol[warp_m * 128 + col] = cs[nf * 2 + e];
                }
        }
        __syncthreads();
        if (tid < 128) {
            float v = scol[0 * 128 + tid] + scol[1 * 128 + tid];   // rows 0-63
            g_partial[(size_t)(bcol * 128 + tid) * PSLOTS + brow * 2 + 0] = v;
        } else {
            int ccol = tid - 128;
            float v = scol[2 * 128 + ccol] + scol[3 * 128 + ccol]; // rows 64-127
            g_partial[(size_t)(bcol * 128 + ccol) * PSLOTS + brow * 2 + 1] = v;
        }
    }
}

// ============================================================
// Kernel 3a: warp-per-row loss terms. 256 blocks x 512 threads.
// ============================================================
__global__ void __launch_bounds__(512) finalize1_k()
{
    const int gw = (blockIdx.x * 512 + threadIdx.x) >> 5;  // row
    const int lane = threadIdx.x & 31;
    const int warp = threadIdx.x >> 5;

    float2 v2 = reinterpret_cast<const float2*>(g_partial + (size_t)gw * PSLOTS)[lane];
    float s = v2.x + v2.y;
    #pragma unroll
    for (int o = 16; o > 0; o >>= 1)
        s += __shfl_down_sync(0xffffffffu, s, o);

    __shared__ float red[16];
    if (lane == 0) {
        float pos = g_pos[gw], diag = g_diag[gw];
        float tot = s - exp2S(diag) + exp2S(pos);
        red[warp] = logf(tot) - 2.0f * pos;
    }
    __syncthreads();
    if (threadIdx.x < 16) {
        float v = red[threadIdx.x];
        #pragma unroll
        for (int o = 8; o > 0; o >>= 1)
            v += __shfl_down_sync(0xffffu, v, o);
        if (threadIdx.x == 0) g_blk[blockIdx.x] = v;
    }
}

// ============================================================
// Kernel 3b: final reduce of 256 block sums.
// ============================================================
__global__ void __launch_bounds__(256) finalize2_k(float* __restrict__ out)
{
    float v = g_blk[threadIdx.x];
    #pragma unroll
    for (int o = 16; o > 0; o >>= 1)
        v += __shfl_down_sync(0xffffffffu, v, o);
    __shared__ float red[8];
    if ((threadIdx.x & 31) == 0) red[threadIdx.x >> 5] = v;
    __syncthreads();
    if (threadIdx.x < 8) {
        float w = red[threadIdx.x];
        #pragma unroll
        for (int o = 4; o > 0; o >>= 1)
            w += __shfl_down_sync(0xffu, w, o);
        if (threadIdx.x == 0) out[0] = w / (float)NROWS;
    }
}

// ============================================================
extern "C" void kernel_launch(void* const* d_in, const int* in_sizes, int n_in,
                              void* d_out, int out_size)
{
    const float* zi = (const float*)d_in[0];
    const float* zj = (const float*)d_in[1];
    float* out = (float*)d_out;

    cudaFuncSetAttribute(gemm_expsum_k,
                         cudaFuncAttributeMaxDynamicSharedMemorySize, SMEM_TOT);

    normpos_k<<<HALF, 128>>>(zi, zj);
    dim3 grid(NROWS / 128, NROWS / 128);   // (32, 32), lower triangle exits
    gemm_expsum_k<<<grid, 256, SMEM_TOT>>>();
    finalize1_k<<<256, 512>>>();
    finalize2_k<<<1, 256>>>(out);
}